// round 2
// baseline (speedup 1.0000x reference)
#include <cuda_runtime.h>

#define B_   16
#define N_   1024
#define H_   224
#define W_   224
#define W4   56          // W_/4
#define KS   23
#define HALF 11
#define SIGMA2X2 18.0f   // 2 * 3.0^2
#define RT   8           // output rows per conv unit
#define RTILES (H_ / RT) // 28
#define NBLK 98          // B_*RTILES*W4 / 256  = 16*28*56/256
#define NTHR 256
#define NTOT (NBLK * NTHR)   // 25088 threads

// Scratch: separable x-accumulation A[B,H,W], 1-D kernel, grid barrier counter.
__device__ float g_A[B_ * H_ * W_];
__device__ float g_k1[KS];
__device__ unsigned int g_bar = 0;

// Software grid barrier: all NBLK blocks are co-resident (NBLK <= 148 SMs).
// Monotonic counter; caller supplies cumulative target.
__device__ __forceinline__ void grid_sync(unsigned int target) {
    __syncthreads();
    if (threadIdx.x == 0) {
        __threadfence();
        atomicAdd(&g_bar, 1u);
        while (*(volatile unsigned int*)&g_bar < target) { }
        __threadfence();
    }
    __syncthreads();
}

__global__ void __launch_bounds__(NTHR, 1)
fused_saliency_kernel(const float* __restrict__ points, float* __restrict__ out) {
    const int tid = blockIdx.x * NTHR + threadIdx.x;

    // ---------------- Phase 0: zero A + compute normalized 1-D Gaussian ----
    {
        float4 z = make_float4(0.f, 0.f, 0.f, 0.f);
        float4* A4 = reinterpret_cast<float4*>(g_A);
        #pragma unroll
        for (int k = 0; k < 8; k++)          // 8 * 25088 = 200704 = B*H*W/4
            A4[tid + k * NTOT] = z;
    }
    if (blockIdx.x == 0 && threadIdx.x < 32) {
        int lane = threadIdx.x;
        float d = (float)lane - (float)(KS - 1) * 0.5f;
        float v = (lane < KS) ? expf(-(d * d) / SIGMA2X2) : 0.0f;
        float s = v;
        #pragma unroll
        for (int off = 16; off > 0; off >>= 1)
            s += __shfl_xor_sync(0xFFFFFFFFu, s, off);
        if (lane < KS) g_k1[lane] = v / s;
    }
    grid_sync(NBLK);

    // ---------------- Phase 1: scatter 1-D x-profiles (global atomics) -----
    if (tid < B_ * N_) {
        float2 p = reinterpret_cast<const float2*>(points)[tid];
        int x = (int)(p.x * (float)W_);   // truncation == astype(int32), nonneg
        int y = (int)(p.y * (float)H_);
        int b = tid >> 10;                // N_ = 1024
        if ((unsigned)y < (unsigned)H_) {
            float* row = g_A + (b * H_ + y) * W_;
            #pragma unroll
            for (int j = 0; j < KS; j++) {
                int c = x + j - HALF;
                if ((unsigned)c < (unsigned)W_)
                    atomicAdd(row + c, g_k1[j]);
            }
        }
    }
    grid_sync(2u * NBLK);

    // ---------------- Phase 2: y-conv, 8-row register tiling ---------------
    {
        // unit -> (b, r-tile, c4); one float4 column, 8 consecutive output rows
        int c4 = tid % W4;
        int t  = tid / W4;
        int rt = t % RTILES;
        int b  = t / RTILES;
        int r0 = rt * RT;

        float w[KS];
        #pragma unroll
        for (int j = 0; j < KS; j++) w[j] = g_k1[j];

        float4 acc[RT];
        #pragma unroll
        for (int k = 0; k < RT; k++) acc[k] = make_float4(0.f, 0.f, 0.f, 0.f);

        const float* Abase = g_A + (b * H_) * W_ + c4 * 4;
        #pragma unroll
        for (int u = 0; u < RT + KS - 1; u++) {   // 30 input rows
            int rr = r0 - HALF + u;
            float4 v = make_float4(0.f, 0.f, 0.f, 0.f);
            if ((unsigned)rr < (unsigned)H_)
                v = *reinterpret_cast<const float4*>(Abase + rr * W_);
            #pragma unroll
            for (int k = 0; k < RT; k++) {
                int j = u - k;                    // compile-time per (u,k)
                if (j >= 0 && j < KS) {
                    acc[k].x = fmaf(w[j], v.x, acc[k].x);
                    acc[k].y = fmaf(w[j], v.y, acc[k].y);
                    acc[k].z = fmaf(w[j], v.z, acc[k].z);
                    acc[k].w = fmaf(w[j], v.w, acc[k].w);
                }
            }
        }
        float* obase = out + (b * H_ + r0) * W_ + c4 * 4;
        #pragma unroll
        for (int k = 0; k < RT; k++)
            *reinterpret_cast<float4*>(obase + k * W_) = acc[k];
    }

    // ---------------- Final arrive: reset barrier for next graph replay ----
    __syncthreads();
    if (threadIdx.x == 0) {
        unsigned int prev = atomicAdd(&g_bar, 1u);
        if (prev == 3u * NBLK - 1u)
            *(volatile unsigned int*)&g_bar = 0u;   // last block resets
    }
}

extern "C" void kernel_launch(void* const* d_in, const int* in_sizes, int n_in,
                              void* d_out, int out_size) {
    const float* points = (const float*)d_in[1];  // d_in[0] = feature_map (unused)
    float* out = (float*)d_out;
    fused_saliency_kernel<<<NBLK, NTHR>>>(points, out);
}

// round 3
// speedup vs baseline: 1.2416x; 1.2416x over previous
#include <cuda_runtime.h>

#define B_   16
#define N_   1024
#define H_   224
#define W_   224
#define W4   56            // W_/4
#define KS   23
#define HALF 11
#define SIGMA2X2 18.0f     // 2 * 3.0^2
#define RPB  32            // output rows per block
#define TILES_Y (H_ / RPB) // 7
#define STRIP (RPB + KS - 1) // 54 input rows per strip
#define RT   8             // register-tiled rows per conv unit
#define NTHR 256
#define NBLK (B_ * TILES_Y) // 112 blocks — one wave

__global__ void __launch_bounds__(NTHR, 1)
saliency_strip_kernel(const float* __restrict__ points, float* __restrict__ out) {
    __shared__ float s_strip[STRIP * W_];   // 54*224*4 = 48384 B
    __shared__ float s_w[KS];

    const int tidx = threadIdx.x;
    const int blk  = blockIdx.x;
    const int b    = blk / TILES_Y;
    const int tile = blk % TILES_Y;
    const int r0   = tile * RPB;            // first output row
    const int ylo  = r0 - HALF;             // strip row 0 == global row ylo

    // ---- Phase 0: zero strip + compute normalized 1-D Gaussian ----
    {
        float4 z = make_float4(0.f, 0.f, 0.f, 0.f);
        float4* s4 = reinterpret_cast<float4*>(s_strip);
        #pragma unroll
        for (int k = tidx; k < STRIP * W4; k += NTHR)
            s4[k] = z;
    }
    if (tidx < 32) {
        float d = (float)tidx - (float)(KS - 1) * 0.5f;
        float v = (tidx < KS) ? expf(-(d * d) / SIGMA2X2) : 0.0f;
        float s = v;
        #pragma unroll
        for (int off = 16; off > 0; off >>= 1)
            s += __shfl_xor_sync(0xFFFFFFFFu, s, off);
        if (tidx < KS) s_w[tidx] = v / s;
    }
    __syncthreads();

    // ---- Phase 1: scan this batch's points, scatter x-profiles into strip ----
    const float2* pts = reinterpret_cast<const float2*>(points) + b * N_;
    #pragma unroll
    for (int i = tidx; i < N_; i += NTHR) {
        float2 p = pts[i];
        int x = (int)(p.x * (float)W_);   // truncation == astype(int32), nonneg
        int y = (int)(p.y * (float)H_);
        int u = y - ylo;                  // strip row
        if ((unsigned)u < (unsigned)STRIP && (unsigned)y < (unsigned)H_) {
            float* row = s_strip + u * W_;
            #pragma unroll
            for (int j = 0; j < KS; j++) {
                int c = x + j - HALF;
                if ((unsigned)c < (unsigned)W_)
                    atomicAdd(row + c, s_w[j]);
            }
        }
    }
    __syncthreads();

    // ---- Phase 2: y-conv, 8-row register tiling, straight from smem ----
    // Units: (RPB/RT)=4 row-tiles x 56 c4 = 224 units; threads 0..223 active.
    if (tidx < (RPB / RT) * W4) {
        int c4 = tidx % W4;
        int rt = tidx / W4;
        int rloc0 = rt * RT;              // output row within block

        float w[KS];
        #pragma unroll
        for (int j = 0; j < KS; j++) w[j] = s_w[j];

        float4 acc[RT];
        #pragma unroll
        for (int k = 0; k < RT; k++) acc[k] = make_float4(0.f, 0.f, 0.f, 0.f);

        // strip rows rloc0 .. rloc0+29 feed output rows rloc0..rloc0+7
        // (rows outside the image were never written -> stay zero, no checks)
        const float4* scol = reinterpret_cast<const float4*>(s_strip) + c4;
        #pragma unroll
        for (int u = 0; u < RT + KS - 1; u++) {
            float4 v = scol[(rloc0 + u) * W4];
            #pragma unroll
            for (int k = 0; k < RT; k++) {
                int j = u - k;            // compile-time per (u,k)
                if (j >= 0 && j < KS) {
                    acc[k].x = fmaf(w[j], v.x, acc[k].x);
                    acc[k].y = fmaf(w[j], v.y, acc[k].y);
                    acc[k].z = fmaf(w[j], v.z, acc[k].z);
                    acc[k].w = fmaf(w[j], v.w, acc[k].w);
                }
            }
        }

        float* obase = out + (b * H_ + r0 + rloc0) * W_ + c4 * 4;
        #pragma unroll
        for (int k = 0; k < RT; k++)
            *reinterpret_cast<float4*>(obase + k * W_) = acc[k];
    }
}

extern "C" void kernel_launch(void* const* d_in, const int* in_sizes, int n_in,
                              void* d_out, int out_size) {
    const float* points = (const float*)d_in[1];  // d_in[0] = feature_map (unused)
    float* out = (float*)d_out;
    saliency_strip_kernel<<<NBLK, NTHR>>>(points, out);
}

// round 4
// speedup vs baseline: 1.9791x; 1.5940x over previous
#include <cuda_runtime.h>

#define B_   16
#define N_   1024
#define H_   224
#define W_   224
#define W4   56               // W_/4
#define KS   23
#define HALF 11
#define SIGMA2X2 18.0f        // 2 * 3.0^2
#define RPB  16               // output rows per block
#define TILES_Y (H_ / RPB)    // 14
#define STRIP (RPB + KS - 1)  // 38 hist rows per strip
#define RT   4                // y-conv: rows per unit -> 4*56 = 224 units
#define XT   16               // x-conv: outputs per unit -> 14*16 = 224 units
#define NTHR 256
#define NBLK (B_ * TILES_Y)   // 224 blocks

__global__ void __launch_bounds__(NTHR, 2)
saliency_hist_kernel(const float* __restrict__ points, float* __restrict__ out) {
    __shared__ float s_hist[STRIP * W_];  // 38*224*4 = 34048 B  (point counts)
    __shared__ float s_B[RPB * W_];       // 16*224*4 = 14336 B  (y-convolved)
    __shared__ float s_w[KS];

    const int tidx = threadIdx.x;
    const int b    = blockIdx.x / TILES_Y;
    const int tile = blockIdx.x % TILES_Y;
    const int r0   = tile * RPB;
    const int ylo  = r0 - HALF;           // hist row 0 == global row ylo

    // ---- Phase 0: zero hist + compute normalized 1-D Gaussian ----
    {
        float4 z = make_float4(0.f, 0.f, 0.f, 0.f);
        float4* h4 = reinterpret_cast<float4*>(s_hist);
        #pragma unroll
        for (int k = tidx; k < STRIP * W4; k += NTHR)
            h4[k] = z;
    }
    if (tidx < 32) {
        float d = (float)tidx - (float)(KS - 1) * 0.5f;
        float v = (tidx < KS) ? expf(-(d * d) / SIGMA2X2) : 0.0f;
        float s = v;
        #pragma unroll
        for (int off = 16; off > 0; off >>= 1)
            s += __shfl_xor_sync(0xFFFFFFFFu, s, off);
        if (tidx < KS) s_w[tidx] = v / s;
    }
    __syncthreads();

    // ---- Phase 1: histogram scatter — ONE atomic per matching point ----
    {
        const float2* pts = reinterpret_cast<const float2*>(points) + b * N_;
        #pragma unroll
        for (int i = tidx; i < N_; i += NTHR) {
            float2 p = pts[i];
            int x = (int)(p.x * (float)W_);   // truncation == astype(int32), nonneg
            int y = (int)(p.y * (float)H_);
            int u = y - ylo;
            if ((unsigned)u < (unsigned)STRIP &&
                (unsigned)x < (unsigned)W_ && (unsigned)y < (unsigned)H_)
                atomicAdd(&s_hist[u * W_ + x], 1.0f);
        }
    }
    __syncthreads();

    // ---- Phase 2: dense y-conv  B[rl][c] = sum_j w[j] * hist[rl+j][c] ----
    if (tidx < (RPB / RT) * W4) {         // 224 units
        int c4  = tidx % W4;
        int rl0 = (tidx / W4) * RT;

        float w[KS];
        #pragma unroll
        for (int j = 0; j < KS; j++) w[j] = s_w[j];

        float4 acc[RT];
        #pragma unroll
        for (int k = 0; k < RT; k++) acc[k] = make_float4(0.f, 0.f, 0.f, 0.f);

        const float4* hc = reinterpret_cast<const float4*>(s_hist) + c4;
        #pragma unroll
        for (int u = 0; u < RT + KS - 1; u++) {   // 26 strip rows
            float4 v = hc[(rl0 + u) * W4];
            #pragma unroll
            for (int k = 0; k < RT; k++) {
                int j = u - k;                    // compile-time per (u,k)
                if (j >= 0 && j < KS) {
                    acc[k].x = fmaf(w[j], v.x, acc[k].x);
                    acc[k].y = fmaf(w[j], v.y, acc[k].y);
                    acc[k].z = fmaf(w[j], v.z, acc[k].z);
                    acc[k].w = fmaf(w[j], v.w, acc[k].w);
                }
            }
        }
        float4* bc = reinterpret_cast<float4*>(s_B) + c4;
        #pragma unroll
        for (int k = 0; k < RT; k++)
            bc[(rl0 + k) * W4] = acc[k];
    }
    __syncthreads();

    // ---- Phase 3: dense x-conv  out[r][c] = sum_j w[j] * B[r][c-11+j] ----
    if (tidx < RPB * (W_ / XT)) {         // 16 rows * 14 tiles = 224 units
        int ct = tidx % (W_ / XT);
        int r  = tidx / (W_ / XT);
        int c0 = ct * XT;

        float w[KS];
        #pragma unroll
        for (int j = 0; j < KS; j++) w[j] = s_w[j];

        float acc[XT];
        #pragma unroll
        for (int k = 0; k < XT; k++) acc[k] = 0.f;

        const float* brow = s_B + r * W_;
        #pragma unroll
        for (int u = 0; u < XT + KS - 1; u++) {   // 38 taps window
            int cc = c0 - HALF + u;
            float v = ((unsigned)cc < (unsigned)W_) ? brow[cc] : 0.f;
            #pragma unroll
            for (int k = 0; k < XT; k++) {
                int j = u - k;
                if (j >= 0 && j < KS)
                    acc[k] = fmaf(w[j], v, acc[k]);
            }
        }

        float4* orow = reinterpret_cast<float4*>(out + (b * H_ + r0 + r) * W_ + c0);
        #pragma unroll
        for (int k = 0; k < XT / 4; k++)
            orow[k] = make_float4(acc[4*k], acc[4*k+1], acc[4*k+2], acc[4*k+3]);
    }
}

extern "C" void kernel_launch(void* const* d_in, const int* in_sizes, int n_in,
                              void* d_out, int out_size) {
    const float* points = (const float*)d_in[1];  // d_in[0] = feature_map (unused)
    float* out = (float*)d_out;
    saliency_hist_kernel<<<NBLK, NTHR>>>(points, out);
}